// round 12
// baseline (speedup 1.0000x reference)
#include <cuda_runtime.h>
#include <cuda_bf16.h>

// WTA2D: per (B,C) row of H*W=3136 fp32, t = 313th-largest, out = (t > x) ? x : 0.
//
// PERSISTENT PIPELINED CTAs: grid of 592 CTAs (4/SM), each loops over ~28 rows
// with ping-pong register sets. Next row's 13 LDG.128 are issued BEFORE the
// current row's selection, so DRAM latency and the barrier-serialized selection
// overlap instead of alternating (de-phases the cross-CTA L1tex queue).
//
// Selection per row (R11, proven exact):
//   fast path: count >=2.0, 1024-bucket histogram over [1.0,2.0) via
//   (u>>13)&0x3FF (monotone there), pick crossing bucket, gather <=64,
//   parallel rank-count. Fallback: iterated raw-byte histogram rounds + ballot
//   bisection (exact for any input).

#define NROW 3136
#define KSEL 313u
#define WLO 0x3F800000u    // 1.0f
#define WHI 0x40000000u    // 2.0f
#define GRID 592

__device__ __forceinline__ unsigned u2k(unsigned u) {
    return (u & 0x80000000u) ? ~u : (u | 0x80000000u);
}
__device__ __forceinline__ float k2f(unsigned k) {
    unsigned u = (k & 0x80000000u) ? (k ^ 0x80000000u) : ~k;
    return __uint_as_float(u);
}

__device__ __forceinline__ void load_row(const float* __restrict__ x, size_t base,
                                         int tid, bool has4, unsigned u[16]) {
    const uint4* xin = reinterpret_cast<const uint4*>(x + base);
#pragma unroll
    for (int s = 0; s < 4; ++s) {
        int p = tid + s * 256;
        if (s < 3 || has4) {
            uint4 f = xin[p];
            u[4*s+0] = f.x; u[4*s+1] = f.y; u[4*s+2] = f.z; u[4*s+3] = f.w;
        }
    }
}

__device__ __forceinline__ void store_row(float* __restrict__ out, size_t base,
                                          int tid, bool has4, const unsigned u[16], float t) {
    float4* po = reinterpret_cast<float4*>(out + base);
#pragma unroll
    for (int s = 0; s < 4; ++s) {
        int p = tid + s * 256;
        if (s < 3 || has4) {
            float4 o;
            float fx = __uint_as_float(u[4*s+0]);
            float fy = __uint_as_float(u[4*s+1]);
            float fz = __uint_as_float(u[4*s+2]);
            float fw = __uint_as_float(u[4*s+3]);
            o.x = (fx < t) ? fx : 0.0f;
            o.y = (fy < t) ? fy : 0.0f;
            o.z = (fz < t) ? fz : 0.0f;
            o.w = (fw < t) ? fw : 0.0f;
            po[p] = o;
        }
    }
}

// Selection over one row held in registers. On entry: hist/gbuf zeroed,
// gcount==0, sb_m==0, all synced. On exit: shared re-zeroed + synced.
__device__ __forceinline__ float select_row(
    const unsigned u[16], bool has4, int tid, int lane, int warp,
    unsigned* hist, unsigned* aboveW, unsigned* pickW, unsigned* gbuf,
    unsigned* sb_b, unsigned* sb_rank, unsigned* sb_m, float* sb_t, int* gcount)
{
    // ---- classify: count >=2.0, histogram [1.0, 2.0) window ----
    unsigned ab = 0;
#pragma unroll
    for (int j = 0; j < 16; ++j) {
        bool valid = (j < 12) || has4;
        unsigned v = u[j];
        if (valid) {
            if (v < 0x80000000u && v >= WHI) ++ab;
            else if (v >= WLO && v < WHI)
                atomicAdd(&hist[(v >> 13) & 0x3FFu], 1u);
        }
    }
#pragma unroll
    for (int off = 16; off >= 1; off >>= 1)
        ab += __shfl_xor_sync(0xFFFFFFFFu, ab, off);
    if (lane == 0) aboveW[warp] = ab;
    __syncthreads();

    unsigned above = 0;
#pragma unroll
    for (int w = 0; w < 8; ++w) above += aboveW[w];

    bool fb = (above >= KSEL);             // block-uniform
    unsigned bsel = 0, rin = 0, m = 0;

    if (!fb) {
        const unsigned rk = KSEL - above;
        uint4 h = reinterpret_cast<const uint4*>(hist)[tid];
        unsigned cc[4] = { h.x, h.y, h.z, h.w };
        unsigned tot = cc[0] + cc[1] + cc[2] + cc[3];
        unsigned s = tot;
#pragma unroll
        for (int off = 1; off <= 16; off <<= 1) {
            unsigned v = __shfl_down_sync(0xFFFFFFFFu, s, off);
            if (lane + off < 32) s += v;
        }
        if (lane == 0) pickW[warp] = s;
        __syncthreads();
        unsigned run = s - tot;
#pragma unroll
        for (int w = 0; w < 8; ++w) if (w > warp) run += pickW[w];
#pragma unroll
        for (int j = 3; j >= 0; --j) {
            unsigned nr = run + cc[j];
            if (nr >= rk && run < rk) {
                *sb_b    = (unsigned)(tid * 4 + j);
                *sb_rank = rk - run;
                *sb_m    = cc[j];
            }
            run = nr;
        }
        __syncthreads();
        fb   = (*sb_m == 0u);
        bsel = *sb_b; rin = *sb_rank; m = *sb_m;
    }

    if (!fb && m <= 64u) {
#pragma unroll
        for (int j = 0; j < 16; ++j) {
            bool valid = (j < 12) || has4;
            unsigned v = u[j];
            if (valid && v >= WLO && v < WHI && ((v >> 13) & 0x3FFu) == bsel) {
                int p = atomicAdd(gcount, 1);
                if (p < 64) gbuf[p] = v;   // positives: raw order == value order
            }
        }
        __syncthreads();
        if (tid < 64) {
            int n = *gcount;
            if (tid < n) {
                unsigned k = gbuf[tid];
                unsigned g = 0, e = 0;
#pragma unroll
                for (int q = 0; q < 16; ++q) {
                    uint4 v = reinterpret_cast<const uint4*>(gbuf)[q];
                    g += (v.x > k) + (v.y > k) + (v.z > k) + (v.w > k);
                    e += (v.x == k) + (v.y == k) + (v.z == k) + (v.w == k);
                }
                if (g < rin && rin <= g + e) *sb_t = __uint_as_float(k);
            }
        }
    } else if (!fb) {
        fb = true;
    }

    if (fb) {
        // ---- generic fallback: iterated byte rounds (exact, any input) ----
        hist[tid] = 0u;
        if (tid == 0) *gcount = 0;
        __syncthreads();
#pragma unroll
        for (int j = 0; j < 16; ++j) {
            bool valid = (j < 12) || has4;
            if (valid) atomicAdd(&hist[u[j] >> 24], 1u);
        }
        __syncthreads();
        if (warp == 0) {
            int o0 = lane * 8;
            unsigned cc[8];
#pragma unroll
            for (int j = 0; j < 8; ++j) {
                int o = o0 + j;
                int u8 = (o < 128) ? (127 - o) : o;
                cc[j] = hist[u8];
            }
            unsigned tot = cc[0]+cc[1]+cc[2]+cc[3]+cc[4]+cc[5]+cc[6]+cc[7];
            unsigned p = tot;
#pragma unroll
            for (int off = 1; off <= 16; off <<= 1) {
                unsigned v = __shfl_up_sync(0xFFFFFFFFu, p, off);
                if (lane >= off) p += v;
            }
            unsigned run = p - tot;
#pragma unroll
            for (int j = 0; j < 8; ++j) {
                unsigned nr = run + cc[j];
                if (nr >= KSEL && run < KSEL) {
                    int o = o0 + j;
                    unsigned u8 = (o < 128) ? (unsigned)(127 - o) : (unsigned)o;
                    *sb_b    = u8 | ((o >= 128) ? 256u : 0u);
                    *sb_rank = KSEL - run;
                    *sb_m    = cc[j];
                }
                run = nr;
            }
        }
        __syncthreads();
        const unsigned X = (*sb_b & 256u) ? 0xFFu : 0u;
        unsigned U  = *sb_b & 0xFFu;
        unsigned K  = X ? (255u - U) : (U + 128u);
        unsigned rk = *sb_rank;
        unsigned mm = *sb_m;
        int bits = 24;
        while (mm > 64u && bits > 0) {
            hist[tid] = 0u;
            __syncthreads();
#pragma unroll
            for (int j = 0; j < 16; ++j) {
                bool valid = (j < 12) || has4;
                if (valid && (u[j] >> bits) == U)
                    atomicAdd(&hist[((u[j] >> (bits - 8)) & 0xFFu) ^ X], 1u);
            }
            __syncthreads();
            if (warp == 0) {
                unsigned rcur = rk;
                const uint4* h4 = reinterpret_cast<const uint4*>(hist) + lane * 2;
                uint4 v0 = h4[0], v1 = h4[1];
                unsigned cc[8] = { v0.x, v0.y, v0.z, v0.w, v1.x, v1.y, v1.z, v1.w };
                unsigned tot = cc[0]+cc[1]+cc[2]+cc[3]+cc[4]+cc[5]+cc[6]+cc[7];
                unsigned s = tot;
#pragma unroll
                for (int off = 1; off <= 16; off <<= 1) {
                    unsigned v = __shfl_down_sync(0xFFFFFFFFu, s, off);
                    if (lane + off < 32) s += v;
                }
                unsigned run = s - tot;
#pragma unroll
                for (int j = 7; j >= 0; --j) {
                    unsigned nr = run + cc[j];
                    if (nr >= rcur && run < rcur) {
                        *sb_b    = (unsigned)(lane * 8 + j);
                        *sb_rank = rcur - run;
                        *sb_m    = cc[j];
                    }
                    run = nr;
                }
            }
            __syncthreads();
            U  = (U << 8) | (*sb_b ^ X);
            K  = (K << 8) | *sb_b;
            rk = *sb_rank;
            mm = *sb_m;
            bits -= 8;
        }
        if (bits > 0) {
#pragma unroll
            for (int j = 0; j < 16; ++j) {
                bool valid = (j < 12) || has4;
                if (valid && (u[j] >> bits) == U) {
                    int p = atomicAdd(gcount, 1);
                    if (p < 64) gbuf[p] = u2k(u[j]);
                }
            }
            __syncthreads();
            if (warp == 0) {
                int n = *gcount; if (n > 64) n = 64;
                unsigned ck0 = (lane      < n) ? gbuf[lane]      : 0u;
                unsigned ck1 = (lane + 32 < n) ? gbuf[lane + 32] : 0u;
                bool a0 = (lane < n), a1 = (lane + 32 < n);
                unsigned r = rk;
                unsigned tk = K << bits;
                for (int b = bits - 1; b >= 0; --b) {
                    bool bit0 = ((ck0 >> b) & 1u) != 0u;
                    bool bit1 = ((ck1 >> b) & 1u) != 0u;
                    unsigned c = __popc(__ballot_sync(0xFFFFFFFFu, a0 && bit0))
                               + __popc(__ballot_sync(0xFFFFFFFFu, a1 && bit1));
                    if (c >= r) { a0 = a0 && bit0; a1 = a1 && bit1; tk |= (1u << b); }
                    else        { r -= c; a0 = a0 && !bit0; a1 = a1 && !bit1; }
                }
                if (lane == 0) *sb_t = k2f(tk);
            }
        } else {
            if (tid == 0) *sb_t = __uint_as_float(U);
        }
    }
    __syncthreads();                       // sb_t visible
    float t = *sb_t;

    // ---- re-zero shared state for the next row ----
    reinterpret_cast<uint4*>(hist)[tid] = make_uint4(0u, 0u, 0u, 0u);
    if (tid < 64) gbuf[tid] = 0u;
    if (tid == 0) { *gcount = 0; *sb_m = 0u; }
    __syncthreads();
    return t;
}

__global__ void __launch_bounds__(256, 4)
wta2d_kernel(const float* __restrict__ x, float* __restrict__ out, int nrows) {
    const int tid  = threadIdx.x;
    const int lane = tid & 31;
    const int warp = tid >> 5;
    const bool has4 = (tid < 16);

    __shared__ unsigned hist[1024];
    __shared__ unsigned aboveW[8], pickW[8];
    __shared__ unsigned gbuf[64];
    __shared__ unsigned sb_b, sb_rank, sb_m;
    __shared__ float sb_t;
    __shared__ int gcount;

    // initial zero
    reinterpret_cast<uint4*>(hist)[tid] = make_uint4(0u, 0u, 0u, 0u);
    if (tid < 64) gbuf[tid] = 0u;
    if (tid == 0) { gcount = 0; sb_m = 0u; }

    unsigned A[16], B[16];
    int row = blockIdx.x;
    if (row >= nrows) return;
    load_row(x, (size_t)row * NROW, tid, has4, A);
    __syncthreads();                       // zeros visible

    bool curA = true;
    while (row < nrows) {
        int nrow = row + GRID;
        if (curA) {
            if (nrow < nrows) load_row(x, (size_t)nrow * NROW, tid, has4, B);
            float t = select_row(A, has4, tid, lane, warp, hist, aboveW, pickW,
                                 gbuf, &sb_b, &sb_rank, &sb_m, &sb_t, &gcount);
            store_row(out, (size_t)row * NROW, tid, has4, A, t);
        } else {
            if (nrow < nrows) load_row(x, (size_t)nrow * NROW, tid, has4, A);
            float t = select_row(B, has4, tid, lane, warp, hist, aboveW, pickW,
                                 gbuf, &sb_b, &sb_rank, &sb_m, &sb_t, &gcount);
            store_row(out, (size_t)row * NROW, tid, has4, B, t);
        }
        curA = !curA;
        row = nrow;
    }
}

extern "C" void kernel_launch(void* const* d_in, const int* in_sizes, int n_in,
                              void* d_out, int out_size) {
    const float* x = (const float*)d_in[0];
    float* out = (float*)d_out;
    int rows = in_sizes[0] / NROW;   // 16384
    int grid = (rows < GRID) ? rows : GRID;
    wta2d_kernel<<<grid, 256>>>(x, out, rows);
}

// round 13
// speedup vs baseline: 1.1983x; 1.1983x over previous
#include <cuda_runtime.h>
#include <cuda_bf16.h>

// WTA2D: per (B,C) row of H*W=3136 fp32, t = 313th-largest, out = (t > x) ? x : 0.
//
// TWO INDEPENDENT HALF-BLOCKS per CTA: warps 0-3 process row 2b, warps 4-7 row
// 2b+1, synced only by named barriers (bar.sync 1/2, 128 threads). The two
// selections run out of phase on the same SM, so one half's serial pick /
// barrier drain overlaps the other half's atomic and memory phases.
//
// Per half (proven R8 skeleton @128 thr): 24 raw keys/thread in regs + 64
// remainder elems in shared; round 1 = 256-bucket shared atomic histogram of
// raw top byte (ordered pick folds the key permutation); loop rounds on the
// sign-folded next byte while bucket > 64; gather <=64, one-warp ballot
// bisection; float-compare masked store.

#define NROW 3136
#define KSEL 313u

__device__ __forceinline__ unsigned u2k(unsigned u) {
    return (u & 0x80000000u) ? ~u : (u | 0x80000000u);
}
__device__ __forceinline__ float k2f(unsigned k) {
    unsigned v = (k & 0x80000000u) ? (k ^ 0x80000000u) : ~k;
    return __uint_as_float(v);
}

#define HBAR(h) asm volatile("bar.sync %0, 128;" :: "r"((h) + 1) : "memory")

__global__ void __launch_bounds__(256, 5)
wta2d_kernel(const float* __restrict__ x, float* __restrict__ out) {
    const int tid   = threadIdx.x;
    const int half  = tid >> 7;            // 0 or 1
    const int htid  = tid & 127;
    const int lane  = tid & 31;
    const int hwarp = (tid >> 5) & 3;      // warp within half
    const size_t base = ((size_t)blockIdx.x * 2 + half) * NROW;

    __shared__ unsigned hist[2][256];
    __shared__ uint4 urem4[2][16];         // last 64 elems per row
    __shared__ unsigned gbuf[2][64];
    __shared__ unsigned sb_d[2], sb_rank[2], sb_m[2];
    __shared__ float sb_t[2];
    __shared__ int gcount[2];

    hist[half][htid]       = 0u;
    hist[half][htid + 128] = 0u;
    if (htid == 0) gcount[half] = 0;

    // ---- load row: 24 elems/thread in regs + 64 remainder to shared ----
    unsigned u[24];
    const uint4* xin = reinterpret_cast<const uint4*>(x + base);
#pragma unroll
    for (int s = 0; s < 6; ++s) {
        uint4 f = xin[htid + s * 128];
        u[4*s+0] = f.x; u[4*s+1] = f.y; u[4*s+2] = f.z; u[4*s+3] = f.w;
    }
    if (htid < 16) urem4[half][htid] = xin[768 + htid];
    HBAR(half);                            // zeros + urem visible

    unsigned myrem = 0u;
    if (htid < 64) myrem = reinterpret_cast<const unsigned*>(urem4[half])[htid];

    // ---- round 1: raw top-byte histogram ----
#pragma unroll
    for (int j = 0; j < 24; ++j) atomicAdd(&hist[half][u[j] >> 24], 1u);
    if (htid < 64) atomicAdd(&hist[half][myrem >> 24], 1u);
    HBAR(half);

    if (hwarp == 0) {
        // ordered slot o (0 = highest key): o<128 -> u8=127-o, else u8=o
        int o0 = lane * 8;
        unsigned cc[8];
#pragma unroll
        for (int j = 0; j < 8; ++j) {
            int o = o0 + j;
            int u8 = (o < 128) ? (127 - o) : o;
            cc[j] = hist[half][u8];
        }
        unsigned tot = cc[0]+cc[1]+cc[2]+cc[3]+cc[4]+cc[5]+cc[6]+cc[7];
        unsigned p = tot;                  // inclusive prefix over lanes (o asc)
#pragma unroll
        for (int off = 1; off <= 16; off <<= 1) {
            unsigned v = __shfl_up_sync(0xFFFFFFFFu, p, off);
            if (lane >= off) p += v;
        }
        unsigned run = p - tot;            // counts at higher keys
#pragma unroll
        for (int j = 0; j < 8; ++j) {
            unsigned nr = run + cc[j];
            if (nr >= KSEL && run < KSEL) {
                int o = o0 + j;
                unsigned u8 = (o < 128) ? (unsigned)(127 - o) : (unsigned)o;
                sb_d[half]    = u8 | ((o >= 128) ? 256u : 0u);
                sb_rank[half] = KSEL - run;
                sb_m[half]    = cc[j];
            }
            run = nr;
        }
    }
    HBAR(half);

    const unsigned X = (sb_d[half] & 256u) ? 0xFFu : 0u;  // sign fold
    unsigned U  = sb_d[half] & 0xFFu;      // raw prefix
    unsigned K  = X ? (255u - U) : (U + 128u);            // key prefix
    unsigned rk = sb_rank[half];
    unsigned m  = sb_m[half];
    int bits = 24;                         // unresolved low bits

    // ---- byte rounds while bucket too big ----
    while (m > 64u && bits > 0) {
        hist[half][htid]       = 0u;
        hist[half][htid + 128] = 0u;
        HBAR(half);
#pragma unroll
        for (int j = 0; j < 24; ++j)
            if ((u[j] >> bits) == U)
                atomicAdd(&hist[half][((u[j] >> (bits - 8)) & 0xFFu) ^ X], 1u);
        if (htid < 64 && (myrem >> bits) == U)
            atomicAdd(&hist[half][((myrem >> (bits - 8)) & 0xFFu) ^ X], 1u);
        HBAR(half);
        if (hwarp == 0) {                  // descending pick over key bytes
            unsigned rcur = rk;
            unsigned cc[8];
#pragma unroll
            for (int j = 0; j < 8; ++j) cc[j] = hist[half][lane * 8 + j];
            unsigned tot = cc[0]+cc[1]+cc[2]+cc[3]+cc[4]+cc[5]+cc[6]+cc[7];
            unsigned s = tot;
#pragma unroll
            for (int off = 1; off <= 16; off <<= 1) {
                unsigned v = __shfl_down_sync(0xFFFFFFFFu, s, off);
                if (lane + off < 32) s += v;
            }
            unsigned run = s - tot;        // counts in higher buckets
#pragma unroll
            for (int j = 7; j >= 0; --j) {
                unsigned nr = run + cc[j];
                if (nr >= rcur && run < rcur) {
                    sb_d[half]    = (unsigned)(lane * 8 + j);   // key byte
                    sb_rank[half] = rcur - run;
                    sb_m[half]    = cc[j];
                }
                run = nr;
            }
        }
        HBAR(half);
        U  = (U << 8) | (sb_d[half] ^ X);
        K  = (K << 8) | sb_d[half];
        rk = sb_rank[half];
        m  = sb_m[half];
        bits -= 8;
    }

    // ---- tail ----
    if (bits > 0) {
        // gather <=64 candidates (key transform only here)
#pragma unroll
        for (int j = 0; j < 24; ++j)
            if ((u[j] >> bits) == U) {
                int p = atomicAdd(&gcount[half], 1);
                if (p < 64) gbuf[half][p] = u2k(u[j]);
            }
        if (htid < 64 && (myrem >> bits) == U) {
            int p = atomicAdd(&gcount[half], 1);
            if (p < 64) gbuf[half][p] = u2k(myrem);
        }
        HBAR(half);
        if (hwarp == 0) {
            int n = gcount[half]; if (n > 64) n = 64;
            unsigned ck0 = (lane      < n) ? gbuf[half][lane]      : 0u;
            unsigned ck1 = (lane + 32 < n) ? gbuf[half][lane + 32] : 0u;
            bool a0 = (lane < n), a1 = (lane + 32 < n);
            unsigned r = rk;
            unsigned tk = K << bits;
            for (int b = bits - 1; b >= 0; --b) {
                bool bit0 = ((ck0 >> b) & 1u) != 0u;
                bool bit1 = ((ck1 >> b) & 1u) != 0u;
                unsigned c = __popc(__ballot_sync(0xFFFFFFFFu, a0 && bit0))
                           + __popc(__ballot_sync(0xFFFFFFFFu, a1 && bit1));
                if (c >= r) { a0 = a0 && bit0; a1 = a1 && bit1; tk |= (1u << b); }
                else        { r -= c; a0 = a0 && !bit0; a1 = a1 && !bit1; }
            }
            if (lane == 0) sb_t[half] = k2f(tk);
        }
    } else {
        // full raw value resolved (mass ties)
        if (htid == 0) sb_t[half] = __uint_as_float(U);
    }
    HBAR(half);
    const float t = sb_t[half];

    // ---- mask + store: float compare ----
    float4* po = reinterpret_cast<float4*>(out + base);
#pragma unroll
    for (int s = 0; s < 6; ++s) {
        float4 o;
        float fx = __uint_as_float(u[4*s+0]);
        float fy = __uint_as_float(u[4*s+1]);
        float fz = __uint_as_float(u[4*s+2]);
        float fw = __uint_as_float(u[4*s+3]);
        o.x = (fx < t) ? fx : 0.0f;
        o.y = (fy < t) ? fy : 0.0f;
        o.z = (fz < t) ? fz : 0.0f;
        o.w = (fw < t) ? fw : 0.0f;
        po[htid + s * 128] = o;
    }
    if (htid < 16) {
        uint4 f = urem4[half][htid];
        float4 o;
        float fx = __uint_as_float(f.x);
        float fy = __uint_as_float(f.y);
        float fz = __uint_as_float(f.z);
        float fw = __uint_as_float(f.w);
        o.x = (fx < t) ? fx : 0.0f;
        o.y = (fy < t) ? fy : 0.0f;
        o.z = (fz < t) ? fz : 0.0f;
        o.w = (fw < t) ? fw : 0.0f;
        po[768 + htid] = o;
    }
}

extern "C" void kernel_launch(void* const* d_in, const int* in_sizes, int n_in,
                              void* d_out, int out_size) {
    const float* x = (const float*)d_in[0];
    float* out = (float*)d_out;
    int rows = in_sizes[0] / NROW;   // 16384
    wta2d_kernel<<<rows / 2, 256>>>(x, out);
}